// round 12
// baseline (speedup 1.0000x reference)
#include <cuda_runtime.h>
#include <cuda_fp16.h>
#include <cstdint>

#define Bn  8
#define Tn  2048
#define Dn  1024
#define HSn 128

// Projected tensors, fp16, natural [B][T][HS] layout.
__device__ __half g_k[Bn * Tn * HSn];
__device__ __half g_q[Bn * Tn * HSn];   // pre-scaled by log2(e)/sqrt(HS)
__device__ __half g_v[Bn * Tn * HSn];
__device__ __half g_wh[3 * HSn * Dn];   // fp16 weights [z][128][1024]
__device__ __half g_xh[Bn * Tn * Dn];   // fp16 copy of x (32 MB)
__device__ __half g_po[2 * Bn * Tn * HSn];   // fp16 split-K partials
__device__ float  g_pm[2 * Bn * Tn];    // log2-domain maxima
__device__ float  g_pl[2 * Bn * Tn];
__device__ int    g_flag[Bn * 16];      // split-K completion flags

__device__ __forceinline__ unsigned packh2(float lo, float hi) {
    unsigned r;
    asm("cvt.rn.f16x2.f32 %0, %1, %2;" : "=r"(r) : "f"(hi), "f"(lo));
    return r;
}

__device__ __forceinline__ float fexp2(float x) {
    float r;
    asm("ex2.approx.f32 %0, %1;" : "=f"(r) : "f"(x));
    return r;
}

__device__ __forceinline__ void mma16(float* c, const unsigned* a,
                                      unsigned b0, unsigned b1) {
    asm volatile(
        "mma.sync.aligned.m16n8k16.row.col.f32.f16.f16.f32 "
        "{%0,%1,%2,%3},{%4,%5,%6,%7},{%8,%9},{%0,%1,%2,%3};"
        : "+f"(c[0]), "+f"(c[1]), "+f"(c[2]), "+f"(c[3])
        : "r"(a[0]), "r"(a[1]), "r"(a[2]), "r"(a[3]), "r"(b0), "r"(b1));
}

__device__ __forceinline__ void ldsm4(unsigned* r, const void* p) {
    unsigned a = (unsigned)__cvta_generic_to_shared(p);
    asm volatile("ldmatrix.sync.aligned.m8n8.x4.shared.b16 {%0,%1,%2,%3}, [%4];"
                 : "=r"(r[0]), "=r"(r[1]), "=r"(r[2]), "=r"(r[3]) : "r"(a));
}

__device__ __forceinline__ void ldsm4t(unsigned* r, const void* p) {
    unsigned a = (unsigned)__cvta_generic_to_shared(p);
    asm volatile("ldmatrix.sync.aligned.m8n8.x4.trans.shared.b16 {%0,%1,%2,%3}, [%4];"
                 : "=r"(r[0]), "=r"(r[1]), "=r"(r[2]), "=r"(r[3]) : "r"(a));
}

__device__ __forceinline__ void cpa16(void* smem_ptr, const void* gptr) {
    unsigned saddr = (unsigned)__cvta_generic_to_shared(smem_ptr);
    asm volatile("cp.async.cg.shared.global [%0], [%1], 16;\n" :: "r"(saddr), "l"(gptr));
}

// ---------------------------------------------------------------------------
// prep: convert x and Wk/Wq/Wv fp32 -> fp16; reset split-K flags.
// ---------------------------------------------------------------------------
__global__ __launch_bounds__(256) void prep_kernel(
    const float* __restrict__ x,
    const float* __restrict__ Wk, const float* __restrict__ Wq,
    const float* __restrict__ Wv)
{
    int bid = blockIdx.x;
    if (bid == 0 && threadIdx.x < Bn * 16) g_flag[threadIdx.x] = 0;
    if (bid < 8192) {
        size_t i = ((size_t)bid * 256 + threadIdx.x) * 8;
        float4 a = *(const float4*)(x + i);
        float4 b = *(const float4*)(x + i + 4);
        uint4 u;
        u.x = packh2(a.x, a.y); u.y = packh2(a.z, a.w);
        u.z = packh2(b.x, b.y); u.w = packh2(b.z, b.w);
        *(uint4*)(g_xh + i) = u;
    } else {
        int id = (bid - 8192) * 256 + threadIdx.x;     // 0..98303
        const float* src = (id < 32768) ? Wk : (id < 65536) ? Wq : Wv;
        int off = (id & 32767) * 4;
        float4 v = *(const float4*)(src + off);
        uint2 u;
        u.x = packh2(v.x, v.y);
        u.y = packh2(v.z, v.w);
        *(uint2*)(g_wh + (size_t)id * 4) = u;
    }
}

// ---------------------------------------------------------------------------
// Projection GEMM (fp16 MMA, BK=64, 3-stage pipeline, one barrier per stage).
// Both operands fp16 via cp.async — no LDG/cvt/STS in the loop.
// ---------------------------------------------------------------------------
#define PST 72
#define PXH (128 * PST)
#define PSTGH (2 * PXH)
#define PROJ_SMEM_BYTES (3 * PSTGH * 2)   // 110592 B

__device__ __forceinline__ void proj_fill(__half* stage, const __half* xsrc,
                                          const __half* wsrc, int t)
{
    #pragma unroll
    for (int j = 0; j < 4; j++) {
        int idx = t + 256 * j;
        int row = idx >> 3;
        int u   = idx & 7;
        cpa16(&stage[row * PST + u * 8],       xsrc + (size_t)row * Dn + u * 8);
        cpa16(&stage[PXH + row * PST + u * 8], wsrc + (size_t)row * Dn + u * 8);
    }
    asm volatile("cp.async.commit_group;\n" ::);
}

__device__ __forceinline__ void proj_mma(const __half* Xs, const __half* Ws,
                                         float acc[2][8][4],
                                         int wm, int wn, int lane)
{
    const int arow = wm * 32 + (lane & 15);
    const int ach  = (lane >> 4) * 8;
    const int brow = wn * 64 + (lane & 7) + (lane >> 4) * 8;
    const int bch  = ((lane >> 3) & 1) * 8;
    #pragma unroll
    for (int ks = 0; ks < 4; ks++) {
        unsigned af[2][4];
        ldsm4(af[0], &Xs[arow * PST + ks * 16 + ach]);
        ldsm4(af[1], &Xs[(arow + 16) * PST + ks * 16 + ach]);
        #pragma unroll
        for (int jp = 0; jp < 4; jp++) {
            unsigned bf[4];
            ldsm4(bf, &Ws[(brow + jp * 16) * PST + ks * 16 + bch]);
            mma16(acc[0][2 * jp],     af[0], bf[0], bf[1]);
            mma16(acc[1][2 * jp],     af[1], bf[0], bf[1]);
            mma16(acc[0][2 * jp + 1], af[0], bf[2], bf[3]);
            mma16(acc[1][2 * jp + 1], af[1], bf[2], bf[3]);
        }
    }
}

__global__ __launch_bounds__(256, 2) void proj_kernel()
{
    extern __shared__ __half psm[];

    const int z = blockIdx.z;
    const __half* wsrc = g_wh + (size_t)z * HSn * Dn;

    const int m0   = blockIdx.x * 128;
    const int t    = threadIdx.x;
    const int lane = t & 31;
    const int w    = t >> 5;
    const int wm   = w & 3;
    const int wn   = w >> 2;
    const int lg   = lane >> 2;
    const int lt   = lane & 3;

    const __half* xbase = g_xh + (size_t)m0 * Dn;

    float acc[2][8][4];
    #pragma unroll
    for (int mf = 0; mf < 2; mf++)
        #pragma unroll
        for (int j = 0; j < 8; j++)
            #pragma unroll
            for (int r = 0; r < 4; r++) acc[mf][j][r] = 0.0f;

    #pragma unroll
    for (int s = 0; s < 2; s++)
        proj_fill(psm + s * PSTGH, xbase + s * 64, wsrc + s * 64, t);

    const int NIT = Dn / 64;   // 16
    for (int i = 0; i < NIT; i++) {
        if (i == NIT - 1) asm volatile("cp.async.wait_group 0;\n" ::);
        else              asm volatile("cp.async.wait_group 1;\n" ::);
        __syncthreads();
        if (i + 2 < NIT)
            proj_fill(psm + ((i + 2) % 3) * PSTGH,
                      xbase + (i + 2) * 64, wsrc + (i + 2) * 64, t);
        int sc = i % 3;
        proj_mma(psm + sc * PSTGH, psm + sc * PSTGH + PXH, acc, wm, wn, lane);
    }

    __half* dst = (z == 0) ? g_k : (z == 1) ? g_q : g_v;
    const float qscale = (z == 1) ? 0.08838834764831845f * 1.4426950408889634f
                                  : 1.0f;
    #pragma unroll
    for (int mf = 0; mf < 2; mf++)
        #pragma unroll
        for (int j = 0; j < 8; j++) {
            int row = m0 + wm * 32 + mf * 16 + lg;
            int col = wn * 64 + j * 8 + 2 * lt;
            *(unsigned*)&dst[(size_t)row * HSn + col] =
                packh2(acc[mf][j][0] * qscale, acc[mf][j][1] * qscale);
            *(unsigned*)&dst[(size_t)(row + 8) * HSn + col] =
                packh2(acc[mf][j][2] * qscale, acc[mf][j][3] * qscale);
        }
}

// ---------------------------------------------------------------------------
// Flash attention with fused split-K merge (last CTA per tile merges).
// ---------------------------------------------------------------------------
#define AST 136
#define KHALF (64 * AST)
#define STGH  (2 * KHALF)
#define ATTN_SMEM_BYTES (3 * STGH * 2)    // 104448 B

__device__ __forceinline__ void attn_issue(__half* stage, const __half* kg,
                                           const __half* vg, int t) {
    __half* Ks = stage;
    __half* Vs = stage + KHALF;
    #pragma unroll
    for (int ch = 0; ch < 4; ch++) {
        int idx = ch * 256 + t;
        int r = idx >> 4;
        int c = (idx & 15) * 8;
        cpa16(&Ks[r * AST + c], kg + (size_t)r * HSn + c);
        cpa16(&Vs[r * AST + c], vg + (size_t)r * HSn + c);
    }
    asm volatile("cp.async.commit_group;\n" ::);
}

__global__ __launch_bounds__(256) void attn_kernel(float* __restrict__ out)
{
    extern __shared__ __half smh[];
    __shared__ int s_old;

    const int b    = blockIdx.x;
    const int item = blockIdx.y;
    const int qbi  = item >> 1;
    const int qb   = 15 - qbi;
    const int sp   = item & 1;
    const int kt0  = sp ? (qb + 1) : 0;
    const int nk   = qb + 1;

    const int t    = threadIdx.x;
    const int lane = t & 31;
    const int w    = t >> 5;
    const int lg   = lane >> 2;
    const int lt   = lane & 3;

    // ---- stage Q tile into stage-0 region; read A-fragments ----
    {
        const uint4* qg = (const uint4*)(g_q + (size_t)(b * Tn + qb * 128) * HSn);
        #pragma unroll
        for (int it = 0; it < 8; it++) {
            int idx = it * 256 + t;
            int r = idx >> 4;
            int c = idx & 15;
            *(uint4*)&smh[r * AST + c * 8] = qg[r * 16 + c];
        }
    }
    __syncthreads();

    unsigned qf[8][4];
    {
        const int qrow = w * 16 + (lane & 15);
        const int qch  = (lane >> 4) * 8;
        #pragma unroll
        for (int ks = 0; ks < 8; ks++)
            ldsm4(qf[ks], &smh[qrow * AST + ks * 16 + qch]);
    }
    __syncthreads();

    float o[16][4];
    #pragma unroll
    for (int j = 0; j < 16; j++)
        #pragma unroll
        for (int r = 0; r < 4; r++) o[j][r] = 0.0f;
    float m0 = -1e30f, m1 = -1e30f, l0 = 0.0f, l1 = 0.0f;

    const int rowg0 = qb * 128 + w * 16 + lg;
    const int rowg1 = rowg0 + 8;

    const __half* kbase = g_k + (size_t)b * Tn * HSn;
    const __half* vbase = g_v + (size_t)b * Tn * HSn;

    attn_issue(smh, kbase + (size_t)kt0 * 64 * HSn, vbase + (size_t)kt0 * 64 * HSn, t);
    if (nk > 1)
        attn_issue(smh + STGH, kbase + (size_t)(kt0 + 1) * 64 * HSn,
                   vbase + (size_t)(kt0 + 1) * 64 * HSn, t);

    const int krow = (lane & 7) + (lane >> 4) * 8;
    const int kch  = ((lane >> 3) & 1) * 8;
    const int vrow = (lane & 7) + ((lane >> 3) & 1) * 8;
    const int vch  = (lane >> 4) * 8;

    for (int ii = 0; ii < nk; ii++) {
        const int kt = kt0 + ii;
        if (ii == nk - 1) asm volatile("cp.async.wait_group 0;\n" ::);
        else              asm volatile("cp.async.wait_group 1;\n" ::);
        __syncthreads();
        if (ii + 2 < nk)
            attn_issue(smh + ((ii + 2) % 3) * STGH,
                       kbase + (size_t)(kt + 2) * 64 * HSn,
                       vbase + (size_t)(kt + 2) * 64 * HSn, t);

        const __half* Ks = smh + (ii % 3) * STGH;
        const __half* Vs = Ks + KHALF;

        float s[8][4];
        #pragma unroll
        for (int j = 0; j < 8; j++)
            #pragma unroll
            for (int r = 0; r < 4; r++) s[j][r] = 0.0f;

        #pragma unroll
        for (int ks = 0; ks < 8; ks++) {
            #pragma unroll
            for (int jp = 0; jp < 4; jp++) {
                unsigned bf[4];
                ldsm4(bf, &Ks[(jp * 16 + krow) * AST + ks * 16 + kch]);
                mma16(s[2 * jp],     qf[ks], bf[0], bf[1]);
                mma16(s[2 * jp + 1], qf[ks], bf[2], bf[3]);
            }
        }

        if (kt * 64 + 63 > qb * 128 + w * 16) {
            #pragma unroll
            for (int j = 0; j < 8; j++) {
                int col = kt * 64 + j * 8 + 2 * lt;
                if (col     > rowg0) s[j][0] = -1e30f;
                if (col + 1 > rowg0) s[j][1] = -1e30f;
                if (col     > rowg1) s[j][2] = -1e30f;
                if (col + 1 > rowg1) s[j][3] = -1e30f;
            }
        }

        float mx0 = -1e30f, mx1 = -1e30f;
        #pragma unroll
        for (int j = 0; j < 8; j++) {
            mx0 = fmaxf(mx0, fmaxf(s[j][0], s[j][1]));
            mx1 = fmaxf(mx1, fmaxf(s[j][2], s[j][3]));
        }
        mx0 = fmaxf(mx0, __shfl_xor_sync(0xffffffffu, mx0, 1));
        mx0 = fmaxf(mx0, __shfl_xor_sync(0xffffffffu, mx0, 2));
        mx1 = fmaxf(mx1, __shfl_xor_sync(0xffffffffu, mx1, 1));
        mx1 = fmaxf(mx1, __shfl_xor_sync(0xffffffffu, mx1, 2));

        float mn0 = fmaxf(m0, mx0);
        float mn1 = fmaxf(m1, mx1);
        float c0 = fexp2(m0 - mn0);
        float c1 = fexp2(m1 - mn1);
        m0 = mn0; m1 = mn1;

        float sum0 = 0.0f, sum1 = 0.0f;
        #pragma unroll
        for (int j = 0; j < 8; j++) {
            s[j][0] = fexp2(s[j][0] - mn0); sum0 += s[j][0];
            s[j][1] = fexp2(s[j][1] - mn0); sum0 += s[j][1];
            s[j][2] = fexp2(s[j][2] - mn1); sum1 += s[j][2];
            s[j][3] = fexp2(s[j][3] - mn1); sum1 += s[j][3];
        }
        sum0 += __shfl_xor_sync(0xffffffffu, sum0, 1);
        sum0 += __shfl_xor_sync(0xffffffffu, sum0, 2);
        sum1 += __shfl_xor_sync(0xffffffffu, sum1, 1);
        sum1 += __shfl_xor_sync(0xffffffffu, sum1, 2);
        l0 = l0 * c0 + sum0;
        l1 = l1 * c1 + sum1;

        #pragma unroll
        for (int j = 0; j < 16; j++) {
            o[j][0] *= c0; o[j][1] *= c0;
            o[j][2] *= c1; o[j][3] *= c1;
        }

        #pragma unroll
        for (int g = 0; g < 4; g++) {
            unsigned a[4];
            a[0] = packh2(s[2 * g][0],     s[2 * g][1]);
            a[1] = packh2(s[2 * g][2],     s[2 * g][3]);
            a[2] = packh2(s[2 * g + 1][0], s[2 * g + 1][1]);
            a[3] = packh2(s[2 * g + 1][2], s[2 * g + 1][3]);
            #pragma unroll
            for (int jq = 0; jq < 8; jq++) {
                unsigned bf[4];
                ldsm4t(bf, &Vs[(16 * g + vrow) * AST + jq * 16 + vch]);
                mma16(o[2 * jq],     a, bf[0], bf[1]);
                mma16(o[2 * jq + 1], a, bf[2], bf[3]);
            }
        }
    }

    const size_t r0 = (size_t)(b * Tn) + rowg0;
    const size_t r1 = (size_t)(b * Tn) + rowg1;

    // ---- publish partials (fp16 O + m + l), then flag ----
    {
        __half* po = g_po + (size_t)sp * (Bn * Tn * HSn);
        #pragma unroll
        for (int j2 = 0; j2 < 16; j2++) {
            int col = j2 * 8 + 2 * lt;
            *(unsigned*)&po[r0 * HSn + col] = packh2(o[j2][0], o[j2][1]);
            *(unsigned*)&po[r1 * HSn + col] = packh2(o[j2][2], o[j2][3]);
        }
        if (lt == 0) {
            g_pm[sp * (Bn * Tn) + r0] = m0;
            g_pl[sp * (Bn * Tn) + r0] = l0;
            g_pm[sp * (Bn * Tn) + r1] = m1;
            g_pl[sp * (Bn * Tn) + r1] = l1;
        }
    }
    __threadfence();
    if (t == 0) s_old = atomicAdd(&g_flag[b * 16 + qbi], 1);
    __syncthreads();

    // ---- last CTA of the pair merges: own regs + peer partials -> out ----
    if (s_old == 1) {
        __threadfence();
        const int osp = 1 - sp;
        const __half* po = g_po + (size_t)osp * (Bn * Tn * HSn);
        float mo0 = g_pm[osp * (Bn * Tn) + r0];
        float lo0 = g_pl[osp * (Bn * Tn) + r0];
        float mo1 = g_pm[osp * (Bn * Tn) + r1];
        float lo1 = g_pl[osp * (Bn * Tn) + r1];

        float mm0 = fmaxf(m0, mo0);
        float ws0 = fexp2(m0 - mm0);
        float wo0 = fexp2(mo0 - mm0);
        float inv0 = 1.0f / (l0 * ws0 + lo0 * wo0);
        float mm1 = fmaxf(m1, mo1);
        float ws1 = fexp2(m1 - mm1);
        float wo1 = fexp2(mo1 - mm1);
        float inv1 = 1.0f / (l1 * ws1 + lo1 * wo1);

        #pragma unroll
        for (int j2 = 0; j2 < 16; j2++) {
            int col = j2 * 8 + 2 * lt;
            float2 p0 = __half22float2(*(const __half2*)&po[r0 * HSn + col]);
            float2 p1 = __half22float2(*(const __half2*)&po[r1 * HSn + col]);
            float2 q0, q1;
            q0.x = (o[j2][0] * ws0 + p0.x * wo0) * inv0;
            q0.y = (o[j2][1] * ws0 + p0.y * wo0) * inv0;
            q1.x = (o[j2][2] * ws1 + p1.x * wo1) * inv1;
            q1.y = (o[j2][3] * ws1 + p1.y * wo1) * inv1;
            *(float2*)&out[r0 * HSn + col] = q0;
            *(float2*)&out[r1 * HSn + col] = q1;
        }
    }
}

// ---------------------------------------------------------------------------
extern "C" void kernel_launch(void* const* d_in, const int* in_sizes, int n_in,
                              void* d_out, int out_size)
{
    const float* x  = (const float*)d_in[0];
    const float* Wk = (const float*)d_in[1];
    const float* Wq = (const float*)d_in[2];
    const float* Wv = (const float*)d_in[3];
    float* out = (float*)d_out;

    prep_kernel<<<8192 + 384, 256>>>(x, Wk, Wq, Wv);

    cudaFuncSetAttribute(proj_kernel, cudaFuncAttributeMaxDynamicSharedMemorySize,
                         PROJ_SMEM_BYTES);
    dim3 pg(Bn * Tn / 128, 1, 3);
    proj_kernel<<<pg, 256, PROJ_SMEM_BYTES>>>();

    cudaFuncSetAttribute(attn_kernel, cudaFuncAttributeMaxDynamicSharedMemorySize,
                         ATTN_SMEM_BYTES);
    dim3 ag(Bn, 32);
    attn_kernel<<<ag, 256, ATTN_SMEM_BYTES>>>(out);
}

// round 13
// speedup vs baseline: 1.0459x; 1.0459x over previous
#include <cuda_runtime.h>
#include <cuda_fp16.h>
#include <cstdint>

#define Bn  8
#define Tn  2048
#define Dn  1024
#define HSn 128

// Projected tensors, fp16, natural [B][T][HS] layout.
__device__ __half g_k[Bn * Tn * HSn];
__device__ __half g_q[Bn * Tn * HSn];   // pre-scaled by log2(e)/sqrt(HS)
__device__ __half g_v[Bn * Tn * HSn];
__device__ __half g_wh[3 * HSn * Dn];   // fp16 weights [z][128][1024]
__device__ __half g_xh[Bn * Tn * Dn];   // fp16 copy of x (32 MB)
__device__ __half g_po[2 * Bn * Tn * HSn];   // fp16 split-K partials
__device__ float  g_pm[2 * Bn * Tn];    // log2-domain maxima
__device__ float  g_pl[2 * Bn * Tn];

__device__ __forceinline__ unsigned packh2(float lo, float hi) {
    unsigned r;
    asm("cvt.rn.f16x2.f32 %0, %1, %2;" : "=r"(r) : "f"(hi), "f"(lo));
    return r;
}

__device__ __forceinline__ float fexp2(float x) {
    float r;
    asm("ex2.approx.f32 %0, %1;" : "=f"(r) : "f"(x));
    return r;
}

__device__ __forceinline__ void mma16(float* c, const unsigned* a,
                                      unsigned b0, unsigned b1) {
    asm volatile(
        "mma.sync.aligned.m16n8k16.row.col.f32.f16.f16.f32 "
        "{%0,%1,%2,%3},{%4,%5,%6,%7},{%8,%9},{%0,%1,%2,%3};"
        : "+f"(c[0]), "+f"(c[1]), "+f"(c[2]), "+f"(c[3])
        : "r"(a[0]), "r"(a[1]), "r"(a[2]), "r"(a[3]), "r"(b0), "r"(b1));
}

__device__ __forceinline__ void ldsm4(unsigned* r, const void* p) {
    unsigned a = (unsigned)__cvta_generic_to_shared(p);
    asm volatile("ldmatrix.sync.aligned.m8n8.x4.shared.b16 {%0,%1,%2,%3}, [%4];"
                 : "=r"(r[0]), "=r"(r[1]), "=r"(r[2]), "=r"(r[3]) : "r"(a));
}

__device__ __forceinline__ void ldsm4t(unsigned* r, const void* p) {
    unsigned a = (unsigned)__cvta_generic_to_shared(p);
    asm volatile("ldmatrix.sync.aligned.m8n8.x4.trans.shared.b16 {%0,%1,%2,%3}, [%4];"
                 : "=r"(r[0]), "=r"(r[1]), "=r"(r[2]), "=r"(r[3]) : "r"(a));
}

__device__ __forceinline__ void cpa16(void* smem_ptr, const void* gptr) {
    unsigned saddr = (unsigned)__cvta_generic_to_shared(smem_ptr);
    asm volatile("cp.async.cg.shared.global [%0], [%1], 16;\n" :: "r"(saddr), "l"(gptr));
}

// ---------------------------------------------------------------------------
// prep: convert x and Wk/Wq/Wv fp32 -> fp16 in one launch.
// ---------------------------------------------------------------------------
__global__ __launch_bounds__(256) void prep_kernel(
    const float* __restrict__ x,
    const float* __restrict__ Wk, const float* __restrict__ Wq,
    const float* __restrict__ Wv)
{
    int bid = blockIdx.x;
    if (bid < 8192) {
        size_t i = ((size_t)bid * 256 + threadIdx.x) * 8;
        float4 a = *(const float4*)(x + i);
        float4 b = *(const float4*)(x + i + 4);
        uint4 u;
        u.x = packh2(a.x, a.y); u.y = packh2(a.z, a.w);
        u.z = packh2(b.x, b.y); u.w = packh2(b.z, b.w);
        *(uint4*)(g_xh + i) = u;
    } else {
        int id = (bid - 8192) * 256 + threadIdx.x;     // 0..98303
        const float* src = (id < 32768) ? Wk : (id < 65536) ? Wq : Wv;
        int off = (id & 32767) * 4;
        float4 v = *(const float4*)(src + off);
        uint2 u;
        u.x = packh2(v.x, v.y);
        u.y = packh2(v.z, v.w);
        *(uint2*)(g_wh + (size_t)id * 4) = u;
    }
}

// ---------------------------------------------------------------------------
// Projection GEMM (fp16 MMA, BK=64, 3-stage pipeline, one barrier per stage).
// Both operands fp16 via cp.async — no LDG/cvt/STS in the loop.
// ---------------------------------------------------------------------------
#define PST 72
#define PXH (128 * PST)
#define PSTGH (2 * PXH)
#define PROJ_SMEM_BYTES (3 * PSTGH * 2)   // 110592 B

__device__ __forceinline__ void proj_fill(__half* stage, const __half* xsrc,
                                          const __half* wsrc, int t)
{
    #pragma unroll
    for (int j = 0; j < 4; j++) {
        int idx = t + 256 * j;
        int row = idx >> 3;
        int u   = idx & 7;
        cpa16(&stage[row * PST + u * 8],       xsrc + (size_t)row * Dn + u * 8);
        cpa16(&stage[PXH + row * PST + u * 8], wsrc + (size_t)row * Dn + u * 8);
    }
    asm volatile("cp.async.commit_group;\n" ::);
}

__device__ __forceinline__ void proj_mma(const __half* Xs, const __half* Ws,
                                         float acc[2][8][4],
                                         int wm, int wn, int lane)
{
    const int arow = wm * 32 + (lane & 15);
    const int ach  = (lane >> 4) * 8;
    const int brow = wn * 64 + (lane & 7) + (lane >> 4) * 8;
    const int bch  = ((lane >> 3) & 1) * 8;
    #pragma unroll
    for (int ks = 0; ks < 4; ks++) {
        unsigned af[2][4];
        ldsm4(af[0], &Xs[arow * PST + ks * 16 + ach]);
        ldsm4(af[1], &Xs[(arow + 16) * PST + ks * 16 + ach]);
        #pragma unroll
        for (int jp = 0; jp < 4; jp++) {
            unsigned bf[4];
            ldsm4(bf, &Ws[(brow + jp * 16) * PST + ks * 16 + bch]);
            mma16(acc[0][2 * jp],     af[0], bf[0], bf[1]);
            mma16(acc[1][2 * jp],     af[1], bf[0], bf[1]);
            mma16(acc[0][2 * jp + 1], af[0], bf[2], bf[3]);
            mma16(acc[1][2 * jp + 1], af[1], bf[2], bf[3]);
        }
    }
}

__global__ __launch_bounds__(256, 2) void proj_kernel()
{
    extern __shared__ __half psm[];

    const int z = blockIdx.z;
    const __half* wsrc = g_wh + (size_t)z * HSn * Dn;

    const int m0   = blockIdx.x * 128;
    const int t    = threadIdx.x;
    const int lane = t & 31;
    const int w    = t >> 5;
    const int wm   = w & 3;
    const int wn   = w >> 2;
    const int lg   = lane >> 2;
    const int lt   = lane & 3;

    const __half* xbase = g_xh + (size_t)m0 * Dn;

    float acc[2][8][4];
    #pragma unroll
    for (int mf = 0; mf < 2; mf++)
        #pragma unroll
        for (int j = 0; j < 8; j++)
            #pragma unroll
            for (int r = 0; r < 4; r++) acc[mf][j][r] = 0.0f;

    #pragma unroll
    for (int s = 0; s < 2; s++)
        proj_fill(psm + s * PSTGH, xbase + s * 64, wsrc + s * 64, t);

    const int NIT = Dn / 64;   // 16
    for (int i = 0; i < NIT; i++) {
        if (i == NIT - 1) asm volatile("cp.async.wait_group 0;\n" ::);
        else              asm volatile("cp.async.wait_group 1;\n" ::);
        __syncthreads();
        if (i + 2 < NIT)
            proj_fill(psm + ((i + 2) % 3) * PSTGH,
                      xbase + (i + 2) * 64, wsrc + (i + 2) * 64, t);
        int sc = i % 3;
        proj_mma(psm + sc * PSTGH, psm + sc * PSTGH + PXH, acc, wm, wn, lane);
    }

    __half* dst = (z == 0) ? g_k : (z == 1) ? g_q : g_v;
    const float qscale = (z == 1) ? 0.08838834764831845f * 1.4426950408889634f
                                  : 1.0f;
    #pragma unroll
    for (int mf = 0; mf < 2; mf++)
        #pragma unroll
        for (int j = 0; j < 8; j++) {
            int row = m0 + wm * 32 + mf * 16 + lg;
            int col = wn * 64 + j * 8 + 2 * lt;
            *(unsigned*)&dst[(size_t)row * HSn + col] =
                packh2(acc[mf][j][0] * qscale, acc[mf][j][1] * qscale);
            *(unsigned*)&dst[(size_t)(row + 8) * HSn + col] =
                packh2(acc[mf][j][2] * qscale, acc[mf][j][3] * qscale);
        }
}

// ---------------------------------------------------------------------------
// Flash attention: fp16 MMA, BM=128, BN=64, split-K x2,
// 4-stage cp.async pipeline (issue BEFORE wait), log2-domain softmax.
// ---------------------------------------------------------------------------
#define AST 136
#define KHALF (64 * AST)
#define STGH  (2 * KHALF)                 // halfs per stage (K + V) = 17408
#define ATTN_SMEM_BYTES (4 * STGH * 2)    // 139264 B

__device__ __forceinline__ void attn_issue(__half* stage, const __half* kg,
                                           const __half* vg, int t) {
    __half* Ks = stage;
    __half* Vs = stage + KHALF;
    #pragma unroll
    for (int ch = 0; ch < 4; ch++) {
        int idx = ch * 256 + t;
        int r = idx >> 4;
        int c = (idx & 15) * 8;
        cpa16(&Ks[r * AST + c], kg + (size_t)r * HSn + c);
        cpa16(&Vs[r * AST + c], vg + (size_t)r * HSn + c);
    }
    asm volatile("cp.async.commit_group;\n" ::);
}

__global__ __launch_bounds__(256) void attn_kernel()
{
    extern __shared__ __half smh[];

    const int b    = blockIdx.x;
    const int item = blockIdx.y;
    const int qb   = 15 - (item >> 1);
    const int sp   = item & 1;
    const int kt0  = sp ? (qb + 1) : 0;
    const int nk   = qb + 1;

    const int t    = threadIdx.x;
    const int lane = t & 31;
    const int w    = t >> 5;
    const int lg   = lane >> 2;
    const int lt   = lane & 3;

    const __half* kbase = g_k + (size_t)b * Tn * HSn;
    const __half* vbase = g_v + (size_t)b * Tn * HSn;

    // ---- issue K/V stages 0,1 FIRST so the DMA overlaps Q staging ----
    attn_issue(smh, kbase + (size_t)kt0 * 64 * HSn, vbase + (size_t)kt0 * 64 * HSn, t);
    if (nk > 1)
        attn_issue(smh + STGH, kbase + (size_t)(kt0 + 1) * 64 * HSn,
                   vbase + (size_t)(kt0 + 1) * 64 * HSn, t);

    // ---- stage Q tile into stage-3 buffer (untouched until ii=1's issue) ----
    __half* Qbuf = smh + 3 * STGH;
    {
        const uint4* qg = (const uint4*)(g_q + (size_t)(b * Tn + qb * 128) * HSn);
        #pragma unroll
        for (int it = 0; it < 8; it++) {
            int idx = it * 256 + t;
            int r = idx >> 4;
            int c = idx & 15;
            *(uint4*)&Qbuf[r * AST + c * 8] = qg[r * 16 + c];
        }
    }
    __syncthreads();

    unsigned qf[8][4];
    {
        const int qrow = w * 16 + (lane & 15);
        const int qch  = (lane >> 4) * 8;
        #pragma unroll
        for (int ks = 0; ks < 8; ks++)
            ldsm4(qf[ks], &Qbuf[qrow * AST + ks * 16 + qch]);
    }

    float o[16][4];
    #pragma unroll
    for (int j = 0; j < 16; j++)
        #pragma unroll
        for (int r = 0; r < 4; r++) o[j][r] = 0.0f;
    float m0 = -1e30f, m1 = -1e30f, l0 = 0.0f, l1 = 0.0f;

    const int rowg0 = qb * 128 + w * 16 + lg;
    const int rowg1 = rowg0 + 8;

    const int krow = (lane & 7) + (lane >> 4) * 8;
    const int kch  = ((lane >> 3) & 1) * 8;
    const int vrow = (lane & 7) + ((lane >> 3) & 1) * 8;
    const int vch  = (lane >> 4) * 8;

    for (int ii = 0; ii < nk; ii++) {
        const int kt = kt0 + ii;
        // issue stage ii+2 BEFORE waiting (target differs from stage being read)
        if (ii + 2 < nk)
            attn_issue(smh + ((ii + 2) & 3) * STGH,
                       kbase + (size_t)(kt + 2) * 64 * HSn,
                       vbase + (size_t)(kt + 2) * 64 * HSn, t);
        const int rem = nk - ii - 1;
        if (rem >= 2)      asm volatile("cp.async.wait_group 2;\n" ::);
        else if (rem == 1) asm volatile("cp.async.wait_group 1;\n" ::);
        else               asm volatile("cp.async.wait_group 0;\n" ::);
        __syncthreads();

        const __half* Ks = smh + (ii & 3) * STGH;
        const __half* Vs = Ks + KHALF;

        float s[8][4];
        #pragma unroll
        for (int j = 0; j < 8; j++)
            #pragma unroll
            for (int r = 0; r < 4; r++) s[j][r] = 0.0f;

        #pragma unroll
        for (int ks = 0; ks < 8; ks++) {
            #pragma unroll
            for (int jp = 0; jp < 4; jp++) {
                unsigned bf[4];
                ldsm4(bf, &Ks[(jp * 16 + krow) * AST + ks * 16 + kch]);
                mma16(s[2 * jp],     qf[ks], bf[0], bf[1]);
                mma16(s[2 * jp + 1], qf[ks], bf[2], bf[3]);
            }
        }

        if (kt * 64 + 63 > qb * 128 + w * 16) {
            #pragma unroll
            for (int j = 0; j < 8; j++) {
                int col = kt * 64 + j * 8 + 2 * lt;
                if (col     > rowg0) s[j][0] = -1e30f;
                if (col + 1 > rowg0) s[j][1] = -1e30f;
                if (col     > rowg1) s[j][2] = -1e30f;
                if (col + 1 > rowg1) s[j][3] = -1e30f;
            }
        }

        float mx0 = -1e30f, mx1 = -1e30f;
        #pragma unroll
        for (int j = 0; j < 8; j++) {
            mx0 = fmaxf(mx0, fmaxf(s[j][0], s[j][1]));
            mx1 = fmaxf(mx1, fmaxf(s[j][2], s[j][3]));
        }
        mx0 = fmaxf(mx0, __shfl_xor_sync(0xffffffffu, mx0, 1));
        mx0 = fmaxf(mx0, __shfl_xor_sync(0xffffffffu, mx0, 2));
        mx1 = fmaxf(mx1, __shfl_xor_sync(0xffffffffu, mx1, 1));
        mx1 = fmaxf(mx1, __shfl_xor_sync(0xffffffffu, mx1, 2));

        float mn0 = fmaxf(m0, mx0);
        float mn1 = fmaxf(m1, mx1);
        float c0 = fexp2(m0 - mn0);
        float c1 = fexp2(m1 - mn1);
        m0 = mn0; m1 = mn1;

        float sum0 = 0.0f, sum1 = 0.0f;
        #pragma unroll
        for (int j = 0; j < 8; j++) {
            s[j][0] = fexp2(s[j][0] - mn0); sum0 += s[j][0];
            s[j][1] = fexp2(s[j][1] - mn0); sum0 += s[j][1];
            s[j][2] = fexp2(s[j][2] - mn1); sum1 += s[j][2];
            s[j][3] = fexp2(s[j][3] - mn1); sum1 += s[j][3];
        }
        sum0 += __shfl_xor_sync(0xffffffffu, sum0, 1);
        sum0 += __shfl_xor_sync(0xffffffffu, sum0, 2);
        sum1 += __shfl_xor_sync(0xffffffffu, sum1, 1);
        sum1 += __shfl_xor_sync(0xffffffffu, sum1, 2);
        l0 = l0 * c0 + sum0;
        l1 = l1 * c1 + sum1;

        #pragma unroll
        for (int j = 0; j < 16; j++) {
            o[j][0] *= c0; o[j][1] *= c0;
            o[j][2] *= c1; o[j][3] *= c1;
        }

        #pragma unroll
        for (int g = 0; g < 4; g++) {
            unsigned a[4];
            a[0] = packh2(s[2 * g][0],     s[2 * g][1]);
            a[1] = packh2(s[2 * g][2],     s[2 * g][3]);
            a[2] = packh2(s[2 * g + 1][0], s[2 * g + 1][1]);
            a[3] = packh2(s[2 * g + 1][2], s[2 * g + 1][3]);
            #pragma unroll
            for (int jq = 0; jq < 8; jq++) {
                unsigned bf[4];
                ldsm4t(bf, &Vs[(16 * g + vrow) * AST + jq * 16 + vch]);
                mma16(o[2 * jq],     a, bf[0], bf[1]);
                mma16(o[2 * jq + 1], a, bf[2], bf[3]);
            }
        }
    }

    // ---- write fp16 partials ----
    {
        __half* po = g_po + (size_t)sp * (Bn * Tn * HSn);
        size_t r0 = (size_t)(b * Tn) + rowg0;
        size_t r1 = (size_t)(b * Tn) + rowg1;
        #pragma unroll
        for (int j2 = 0; j2 < 16; j2++) {
            int col = j2 * 8 + 2 * lt;
            *(unsigned*)&po[r0 * HSn + col] = packh2(o[j2][0], o[j2][1]);
            *(unsigned*)&po[r1 * HSn + col] = packh2(o[j2][2], o[j2][3]);
        }
        if (lt == 0) {
            g_pm[sp * (Bn * Tn) + r0] = m0;
            g_pl[sp * (Bn * Tn) + r0] = l0;
            g_pm[sp * (Bn * Tn) + r1] = m1;
            g_pl[sp * (Bn * Tn) + r1] = l1;
        }
    }
}

// ---------------------------------------------------------------------------
__global__ __launch_bounds__(256) void merge_kernel(float* __restrict__ out)
{
    int i8 = blockIdx.x * 256 + threadIdx.x;      // 8 output floats each
    size_t base = (size_t)i8 * 8;
    int row = (int)(base >> 7);
    float m0 = g_pm[row], m1 = g_pm[Bn * Tn + row];
    float l0 = g_pl[row], l1 = g_pl[Bn * Tn + row];
    float m  = fmaxf(m0, m1);
    float w0 = fexp2(m0 - m);
    float w1 = fexp2(m1 - m);
    float inv = 1.0f / (l0 * w0 + l1 * w1);
    uint4 ua = *(const uint4*)(g_po + base);
    uint4 uc = *(const uint4*)(g_po + (size_t)(Bn * Tn * HSn) + base);
    const unsigned* pa = &ua.x;
    const unsigned* pc = &uc.x;
    float r[8];
    #pragma unroll
    for (int q = 0; q < 4; q++) {
        float2 a = __half22float2(*(const __half2*)&pa[q]);
        float2 c = __half22float2(*(const __half2*)&pc[q]);
        r[2 * q]     = (a.x * w0 + c.x * w1) * inv;
        r[2 * q + 1] = (a.y * w0 + c.y * w1) * inv;
    }
    *(float4*)&out[base]     = make_float4(r[0], r[1], r[2], r[3]);
    *(float4*)&out[base + 4] = make_float4(r[4], r[5], r[6], r[7]);
}

// ---------------------------------------------------------------------------
extern "C" void kernel_launch(void* const* d_in, const int* in_sizes, int n_in,
                              void* d_out, int out_size)
{
    const float* x  = (const float*)d_in[0];
    const float* Wk = (const float*)d_in[1];
    const float* Wq = (const float*)d_in[2];
    const float* Wv = (const float*)d_in[3];
    float* out = (float*)d_out;

    prep_kernel<<<8192 + 384, 256>>>(x, Wk, Wq, Wv);

    cudaFuncSetAttribute(proj_kernel, cudaFuncAttributeMaxDynamicSharedMemorySize,
                         PROJ_SMEM_BYTES);
    dim3 pg(Bn * Tn / 128, 1, 3);
    proj_kernel<<<pg, 256, PROJ_SMEM_BYTES>>>();

    cudaFuncSetAttribute(attn_kernel, cudaFuncAttributeMaxDynamicSharedMemorySize,
                         ATTN_SMEM_BYTES);
    dim3 ag(Bn, 32);
    attn_kernel<<<ag, 256, ATTN_SMEM_BYTES>>>();

    merge_kernel<<<(Bn * Tn * HSn / 8) / 256, 256>>>(out);
}